// round 7
// baseline (speedup 1.0000x reference)
#include <cuda_runtime.h>
#include <math.h>
#include <cstdint>

#define LSEQ   1024
#define NBATCH 64
#define NCH    64
#define NSTEP  1056          /* steps per strip: 1024 + 31 + pad */
#define BIGC   1.0e10f
#define LOG2E  1.4426950408889634f
#define LN2F   0.6931471805599453f

/* Warp-step-major scratch: g_Dw[b][w][s][q], q = i & 63 (w = i>>6),
   value = D[i][jj]*log2(e) with jj = s - (q>>1). 277 MB. Slots with
   jj outside [0,1023] are never written and stay 0 (harmless). */
__device__ float g_Dw[(size_t)NBATCH * 16 * NSTEP * 64];

__device__ __forceinline__ float ex2(float z) {
    float r; asm("ex2.approx.f32 %0, %1;" : "=f"(r) : "f"(z)); return r;
}
__device__ __forceinline__ float lg2(float z) {
    float r; asm("lg2.approx.f32 %0, %1;" : "=f"(r) : "f"(z)); return r;
}
__device__ __forceinline__ uint32_t f2tf32(float v) {
    uint32_t r; asm("cvt.rna.tf32.f32 %0, %1;" : "=r"(r) : "f"(v)); return r;
}
/* softmin in base-2 domain: -log2(2^-a + 2^-u + 2^-lf), 3 MUFU */
__device__ __forceinline__ float softmin3(float a, float u, float lf) {
    float mn1 = fminf(a, u);
    float mx1 = fmaxf(a, u);
    float m   = fminf(mn1, lf);
    float M   = fmaxf(mx1, lf);
    float med = fmaxf(mn1, fminf(mx1, lf));
    float e   = 1.0f + ex2(m - med) + ex2(m - M);
    return m - lg2(e);
}

/* ------------------------------------------------------------------ */
/* Kernel A: D = (x2 + y2 - 2*x.y^T) * log2(e) via tf32 mma.sync,     */
/* written into the warp-step-major layout g_Dw.                       */
/* ------------------------------------------------------------------ */
__global__ void __launch_bounds__(256)
compute_D_kernel(const float* __restrict__ x, const float* __restrict__ y) {
    const int b  = blockIdx.y;
    const int ti = blockIdx.x >> 4;
    const int tj = blockIdx.x & 15;
    const int i0 = ti * 64, j0 = tj * 64;

    __shared__ float sbuf[2 * 64 * 68];    /* xs[64][68] | ys[64][68]; reused as Dt_T[64][67] */
    __shared__ float sx2[64], sy2[64];
    float* xs = sbuf;
    float* ys = sbuf + 64 * 68;

    const int tid = threadIdx.x;
    const float4* xb4 = (const float4*)(x + ((size_t)b * LSEQ + i0) * NCH);
    const float4* yb4 = (const float4*)(y + ((size_t)b * LSEQ + j0) * NCH);

#pragma unroll
    for (int k = 0; k < 4; k++) {
        int e = tid + 256 * k;
        int r = e >> 4, c4v = e & 15;
        float4 vx = xb4[r * 16 + c4v];
        float4 vy = yb4[r * 16 + c4v];
        vx.x = __uint_as_float(f2tf32(vx.x)); vx.y = __uint_as_float(f2tf32(vx.y));
        vx.z = __uint_as_float(f2tf32(vx.z)); vx.w = __uint_as_float(f2tf32(vx.w));
        vy.x = __uint_as_float(f2tf32(vy.x)); vy.y = __uint_as_float(f2tf32(vy.y));
        vy.z = __uint_as_float(f2tf32(vy.z)); vy.w = __uint_as_float(f2tf32(vy.w));
        *(float4*)&xs[r * 68 + c4v * 4] = vx;
        *(float4*)&ys[r * 68 + c4v * 4] = vy;
    }
    __syncthreads();

    if (tid < 64) {
        float s = 0.f;
#pragma unroll
        for (int c = 0; c < 64; c++) { float v = xs[tid * 68 + c]; s += v * v; }
        sx2[tid] = s;
    } else if (tid < 128) {
        int r = tid - 64;
        float s = 0.f;
#pragma unroll
        for (int c = 0; c < 64; c++) { float v = ys[r * 68 + c]; s += v * v; }
        sy2[r] = s;
    }
    __syncthreads();

    const int wrp  = tid >> 5, lane = tid & 31;
    const int wr   = wrp & 3, wc = wrp >> 2;
    const int r4   = lane >> 2, c4 = lane & 3;
    const float* As = xs + (wr * 16) * 68;
    const float* Bs = ys + (wc * 32) * 68;

    float cc[4][4];
#pragma unroll
    for (int nt = 0; nt < 4; nt++)
#pragma unroll
        for (int q = 0; q < 4; q++) cc[nt][q] = 0.f;

#pragma unroll
    for (int k0 = 0; k0 < 64; k0 += 8) {
        uint32_t a0 = __float_as_uint(As[(r4)     * 68 + k0 + c4]);
        uint32_t a1 = __float_as_uint(As[(r4 + 8) * 68 + k0 + c4]);
        uint32_t a2 = __float_as_uint(As[(r4)     * 68 + k0 + c4 + 4]);
        uint32_t a3 = __float_as_uint(As[(r4 + 8) * 68 + k0 + c4 + 4]);
#pragma unroll
        for (int nt = 0; nt < 4; nt++) {
            uint32_t b0 = __float_as_uint(Bs[(nt * 8 + r4) * 68 + k0 + c4]);
            uint32_t b1 = __float_as_uint(Bs[(nt * 8 + r4) * 68 + k0 + c4 + 4]);
            asm volatile(
                "mma.sync.aligned.m16n8k8.row.col.f32.tf32.tf32.f32 "
                "{%0,%1,%2,%3}, {%4,%5,%6,%7}, {%8,%9}, {%0,%1,%2,%3};"
                : "+f"(cc[nt][0]), "+f"(cc[nt][1]), "+f"(cc[nt][2]), "+f"(cc[nt][3])
                : "r"(a0), "r"(a1), "r"(a2), "r"(a3), "r"(b0), "r"(b1));
        }
    }
    __syncthreads();                  /* xs/ys dead -> reuse as Dt_T */

    float* Dt = sbuf;                 /* Dt_T[jl][il], stride 67 */
    const int row0 = wr * 16 + r4;
#pragma unroll
    for (int nt = 0; nt < 4; nt++) {
        int colb = wc * 32 + nt * 8 + 2 * c4;
        Dt[colb * 67 + row0]           = (sx2[row0]     + sy2[colb]     - 2.0f * cc[nt][0]) * LOG2E;
        Dt[(colb + 1) * 67 + row0]     = (sx2[row0]     + sy2[colb + 1] - 2.0f * cc[nt][1]) * LOG2E;
        Dt[colb * 67 + row0 + 8]       = (sx2[row0 + 8] + sy2[colb]     - 2.0f * cc[nt][2]) * LOG2E;
        Dt[(colb + 1) * 67 + row0 + 8] = (sx2[row0 + 8] + sy2[colb + 1] - 2.0f * cc[nt][3]) * LOG2E;
    }
    __syncthreads();

    /* write to warp-step-major layout: row s -> 64 contiguous floats   */
    /* lane li supplies q = 2li, 2li+1 (jl = so - li).                  */
    const size_t gbase = ((size_t)(b * 16 + ti) * NSTEP) * 64;
    for (int so = wrp; so < 95; so += 8) {
        int s  = j0 + so;
        int lo = so > 63 ? so - 63 : 0;
        int hi = so < 31 ? so : 31;
        if (lane >= lo && lane <= hi) {
            int jl = so - lane;
            float2 pv = make_float2(Dt[jl * 67 + 2 * lane], Dt[jl * 67 + 2 * lane + 1]);
            *(float2*)(g_Dw + gbase + (size_t)s * 64 + 2 * lane) = pv;
        }
    }
}

/* ------------------------------------------------------------------ */
/* Kernel B: 2 rows per lane, 16 warps per batch, TWO batches per CTA  */
/* (warps 0-15 -> batch 2*bid, warps 16-31 -> batch 2*bid+1) to get    */
/* 8 warps/SMSP of latency hiding. One shfl + one ring op per 2 cells, */
/* double-buffered float2 D prefetch, unguarded body.                  */
/* ------------------------------------------------------------------ */
#define CH      16
#define NCHUNK  66
#define KOFF    3
#define NWARP   16
#define NROUNDS (KOFF * (NWARP - 1) + NCHUNK)   /* 111 */

__global__ void __launch_bounds__(1024)
sdtw_pipeline_kernel(float* __restrict__ out) {
    const int tid  = threadIdx.x;
    const int w    = tid >> 5;
    const int l    = tid & 31;
    const int half = w >> 4;                 /* 0 or 1: which batch       */
    const int wh   = w & 15;                 /* warp index within batch   */
    const int b    = blockIdx.x * 2 + half;

    __shared__ float rb[2][NWARP - 1][128];  /* per-half boundary rings */

    for (int e = tid; e < 2 * (NWARP - 1) * 128; e += 1024) ((float*)rb)[e] = BIGC;
    __syncthreads();

    float v1_0 = BIGC, v1_1 = BIGC;                     /* left values rows r0, r1 */
    float u0_prev = (wh == 0 && l == 0) ? 0.0f : BIGC;  /* diag for r0             */
    float result  = 0.0f;

    const float* dpB = g_Dw + ((size_t)(b * NWARP + wh) * NSTEP) * 64 + 2 * l;
    float*       rbw = (wh < NWARP - 1) ? rb[half][wh] : rb[half][0];
    const float* rbr = (wh > 0) ? rb[half][wh - 1] : rb[half][0];

    float2 dv[CH];
    if (wh == 0) {
#pragma unroll
        for (int k = 0; k < CH; k++) dv[k] = *(const float2*)(dpB + (size_t)k * 64);
    }

    for (int r = 0; r < NROUNDS; r++) {
        const int c  = r - KOFF * wh;
        const int cn = c + 1;

        float2 dn[CH];
        const bool pf = (cn >= 0) && (cn < NCHUNK);
        if (pf) {
            const float* dpn = dpB + (size_t)(cn * CH) * 64;
#pragma unroll
            for (int k = 0; k < CH; k++) dn[k] = *(const float2*)(dpn + (size_t)k * 64);
        }

        if (c >= 0 && c < NCHUNK) {
            const int sc = c * CH;
#pragma unroll
            for (int k = 0; k < CH; k++) {
                const int s = sc + k;
                float rv = rbr[(s + 1) & 127];              /* broadcast LDS */
                float u0 = __shfl_up_sync(0xffffffffu, v1_1, 1);
                if (l == 0) u0 = (wh == 0) ? BIGC : rv;
                /* cell (r0, j): diag=u0_prev, up=u0, left=v1_0 */
                float nv0 = dv[k].x + softmin3(u0_prev, u0, v1_0);
                /* cell (r1, j): diag=v1_0(old), up=nv0, left=v1_1 */
                float nv1 = dv[k].y + softmin3(v1_0, nv0, v1_1);
                if (l == 31) {
                    if (wh < NWARP - 1) rbw[(s - 30) & 127] = nv1;
                    else if (s == 1054) result = nv1;       /* R[1024][1024] */
                }
                v1_0    = nv0;
                v1_1    = nv1;
                u0_prev = u0;
            }
        }

        if (pf) {
#pragma unroll
            for (int k = 0; k < CH; k++) dv[k] = dn[k];
        }
        __syncthreads();
    }

    if (wh == NWARP - 1 && l == 31) out[b] = result * LN2F;
}

/* ------------------------------------------------------------------ */
extern "C" void kernel_launch(void* const* d_in, const int* in_sizes, int n_in,
                              void* d_out, int out_size) {
    (void)in_sizes; (void)n_in; (void)out_size;
    const float* x = (const float*)d_in[0];
    const float* y = (const float*)d_in[1];
    float* out = (float*)d_out;

    dim3 gridA(256, NBATCH);
    compute_D_kernel<<<gridA, 256>>>(x, y);
    sdtw_pipeline_kernel<<<NBATCH / 2, 1024>>>(out);
}

// round 8
// speedup vs baseline: 1.6117x; 1.6117x over previous
#include <cuda_runtime.h>
#include <math.h>
#include <cstdint>

#define LSEQ   1024
#define NBATCH 64
#define NCH    64
#define NSTEP  1056          /* steps per strip: 1024 + 31 + pad */
#define BIGC   1.0e10f
#define LOG2E  1.4426950408889634f
#define LN2F   0.6931471805599453f

/* Strip-step-major scratch: g_D1[b][w][s][l] = D[32w+l][s-l] * log2(e).
   277 MB. Slots with s-l outside [0,1023] are never written and stay 0
   (zero-init, never overwritten -> deterministic; junk self-quenches). */
__device__ float g_D1[(size_t)NBATCH * 32 * NSTEP * 32];

__device__ __forceinline__ float ex2(float z) {
    float r; asm("ex2.approx.f32 %0, %1;" : "=f"(r) : "f"(z)); return r;
}
__device__ __forceinline__ float lg2(float z) {
    float r; asm("lg2.approx.f32 %0, %1;" : "=f"(r) : "f"(z)); return r;
}
__device__ __forceinline__ uint32_t f2tf32(float v) {
    uint32_t r; asm("cvt.rna.tf32.f32 %0, %1;" : "=r"(r) : "f"(v)); return r;
}
/* softmin in base-2 domain: -log2(2^-a + 2^-u + 2^-lf), 3 MUFU */
__device__ __forceinline__ float softmin3(float a, float u, float lf) {
    float mn1 = fminf(a, u);
    float mx1 = fmaxf(a, u);
    float m   = fminf(mn1, lf);
    float M   = fmaxf(mx1, lf);
    float med = fmaxf(mn1, fminf(mx1, lf));
    float e   = 1.0f + ex2(m - med) + ex2(m - M);
    return m - lg2(e);
}

/* ------------------------------------------------------------------ */
/* Kernel A: D = (x2 + y2 - 2*x.y^T) * log2(e) via tf32 mma.sync,     */
/* written into the strip-step-major layout g_D1.                      */
/* ------------------------------------------------------------------ */
__global__ void __launch_bounds__(256)
compute_D_kernel(const float* __restrict__ x, const float* __restrict__ y) {
    const int b  = blockIdx.y;
    const int ti = blockIdx.x >> 4;
    const int tj = blockIdx.x & 15;
    const int i0 = ti * 64, j0 = tj * 64;

    __shared__ float sbuf[2 * 64 * 68];    /* xs[64][68] | ys[64][68]; reused as Dt_T[64][67] */
    __shared__ float sx2[64], sy2[64];
    float* xs = sbuf;
    float* ys = sbuf + 64 * 68;

    const int tid = threadIdx.x;
    const float4* xb4 = (const float4*)(x + ((size_t)b * LSEQ + i0) * NCH);
    const float4* yb4 = (const float4*)(y + ((size_t)b * LSEQ + j0) * NCH);

#pragma unroll
    for (int k = 0; k < 4; k++) {
        int e = tid + 256 * k;
        int r = e >> 4, c4v = e & 15;
        float4 vx = xb4[r * 16 + c4v];
        float4 vy = yb4[r * 16 + c4v];
        vx.x = __uint_as_float(f2tf32(vx.x)); vx.y = __uint_as_float(f2tf32(vx.y));
        vx.z = __uint_as_float(f2tf32(vx.z)); vx.w = __uint_as_float(f2tf32(vx.w));
        vy.x = __uint_as_float(f2tf32(vy.x)); vy.y = __uint_as_float(f2tf32(vy.y));
        vy.z = __uint_as_float(f2tf32(vy.z)); vy.w = __uint_as_float(f2tf32(vy.w));
        *(float4*)&xs[r * 68 + c4v * 4] = vx;
        *(float4*)&ys[r * 68 + c4v * 4] = vy;
    }
    __syncthreads();

    if (tid < 64) {
        float s = 0.f;
#pragma unroll
        for (int c = 0; c < 64; c++) { float v = xs[tid * 68 + c]; s += v * v; }
        sx2[tid] = s;
    } else if (tid < 128) {
        int r = tid - 64;
        float s = 0.f;
#pragma unroll
        for (int c = 0; c < 64; c++) { float v = ys[r * 68 + c]; s += v * v; }
        sy2[r] = s;
    }
    __syncthreads();

    const int wrp  = tid >> 5, lane = tid & 31;
    const int wr   = wrp & 3, wc = wrp >> 2;
    const int r4   = lane >> 2, c4 = lane & 3;
    const float* As = xs + (wr * 16) * 68;
    const float* Bs = ys + (wc * 32) * 68;

    float cc[4][4];
#pragma unroll
    for (int nt = 0; nt < 4; nt++)
#pragma unroll
        for (int q = 0; q < 4; q++) cc[nt][q] = 0.f;

#pragma unroll
    for (int k0 = 0; k0 < 64; k0 += 8) {
        uint32_t a0 = __float_as_uint(As[(r4)     * 68 + k0 + c4]);
        uint32_t a1 = __float_as_uint(As[(r4 + 8) * 68 + k0 + c4]);
        uint32_t a2 = __float_as_uint(As[(r4)     * 68 + k0 + c4 + 4]);
        uint32_t a3 = __float_as_uint(As[(r4 + 8) * 68 + k0 + c4 + 4]);
#pragma unroll
        for (int nt = 0; nt < 4; nt++) {
            uint32_t b0 = __float_as_uint(Bs[(nt * 8 + r4) * 68 + k0 + c4]);
            uint32_t b1 = __float_as_uint(Bs[(nt * 8 + r4) * 68 + k0 + c4 + 4]);
            asm volatile(
                "mma.sync.aligned.m16n8k8.row.col.f32.tf32.tf32.f32 "
                "{%0,%1,%2,%3}, {%4,%5,%6,%7}, {%8,%9}, {%0,%1,%2,%3};"
                : "+f"(cc[nt][0]), "+f"(cc[nt][1]), "+f"(cc[nt][2]), "+f"(cc[nt][3])
                : "r"(a0), "r"(a1), "r"(a2), "r"(a3), "r"(b0), "r"(b1));
        }
    }
    __syncthreads();                  /* xs/ys dead -> reuse as Dt_T */

    float* Dt = sbuf;                 /* Dt_T[jl][il], stride 67 */
    const int row0 = wr * 16 + r4;
#pragma unroll
    for (int nt = 0; nt < 4; nt++) {
        int colb = wc * 32 + nt * 8 + 2 * c4;
        Dt[colb * 67 + row0]           = (sx2[row0]     + sy2[colb]     - 2.0f * cc[nt][0]) * LOG2E;
        Dt[(colb + 1) * 67 + row0]     = (sx2[row0]     + sy2[colb + 1] - 2.0f * cc[nt][1]) * LOG2E;
        Dt[colb * 67 + row0 + 8]       = (sx2[row0 + 8] + sy2[colb]     - 2.0f * cc[nt][2]) * LOG2E;
        Dt[(colb + 1) * 67 + row0 + 8] = (sx2[row0 + 8] + sy2[colb + 1] - 2.0f * cc[nt][3]) * LOG2E;
    }
    __syncthreads();

    /* write to strip-step-major layout: strip w = 2*ti + h owns rows  */
    /* 32h..32h+31 of this tile; lane l writes D[i0+32h+l][j0+so-l]     */
    /* at g_D1[b][w][j0+so][l]  (one 128B store per (h,so)).            */
    const int h  = wrp & 1;           /* strip half within tile        */
    const int w4 = wrp >> 1;          /* 0..3                          */
    const size_t gbase = ((size_t)(b * 32 + ti * 2 + h) * NSTEP + j0) * 32;
    for (int so = w4; so < 95; so += 4) {
        int jl = so - lane;
        if (jl >= 0 && jl < 64) {
            g_D1[gbase + (size_t)so * 32 + lane] = Dt[jl * 67 + 32 * h + lane];
        }
    }
}

/* ------------------------------------------------------------------ */
/* Kernel B: R5 structure (32 warps x 1 row/lane, unguarded, lg2)     */
/* with CH=8 / KOFF=5 -> pipeline-fill lag 40 steps (was 48).          */
/* ------------------------------------------------------------------ */
#define CH      8
#define NCHUNK  132                     /* 132*8 = 1056 >= 1055 steps */
#define KOFF    5
#define NROUNDS (KOFF * 31 + NCHUNK)    /* 287 */

__global__ void __launch_bounds__(1024)
sdtw_pipeline_kernel(float* __restrict__ out) {
    const int b   = blockIdx.x;
    const int tid = threadIdx.x;
    const int w   = tid >> 5;
    const int l   = tid & 31;

    __shared__ float rb[31][128];       /* boundary rings: rb[w] fed by warp w lane 31 */

    for (int e = tid; e < 31 * 128; e += 1024) ((float*)rb)[e] = BIGC;
    __syncthreads();

    float v1     = BIGC;                            /* own value at step s-1 (left) */
    float u_prev = (w == 0 && l == 0) ? 0.0f : BIGC;/* diag operand                 */
    float result = 0.0f;

    const float* dp  = g_D1 + ((size_t)(b * 32 + w) * NSTEP) * 32 + l;
    float*       rbw = (w < 31) ? rb[w] : rb[0];
    const float* rbr = (w > 0) ? rb[w - 1] : rb[0];

    float dv[CH];
    if (w == 0) {                        /* warp 0 preloads its chunk 0 */
#pragma unroll
        for (int k = 0; k < CH; k++) dv[k] = dp[(size_t)k * 32];
    }

    for (int r = 0; r < NROUNDS; r++) {
        const int c  = r - KOFF * w;
        const int cn = c + 1;

        /* prefetch next chunk (consumed next round) */
        float dn[CH];
        const bool pf = (cn >= 0) && (cn < NCHUNK);
        if (pf) {
            const float* dpn = dp + (size_t)(cn * CH) * 32;
#pragma unroll
            for (int k = 0; k < CH; k++) dn[k] = dpn[(size_t)k * 32];
        }

        if (c >= 0 && c < NCHUNK) {
            const int sc = c * CH;
#pragma unroll
            for (int k = 0; k < CH; k++) {
                const int s = sc + k;
                float rv = rbr[(s + 1) & 127];              /* broadcast LDS */
                float u  = __shfl_up_sync(0xffffffffu, v1, 1);
                if (l == 0) u = (w == 0) ? BIGC : rv;
                float nv = dv[k] + softmin3(u_prev, u, v1);
                if (l == 31) {
                    if (w < 31) rbw[(s - 30) & 127] = nv;
                    else if (s == 1054) result = nv;        /* R[1024][1024] */
                }
                v1     = nv;
                u_prev = u;
            }
        }

        if (pf) {
#pragma unroll
            for (int k = 0; k < CH; k++) dv[k] = dn[k];
        }
        __syncthreads();
    }

    if (w == 31 && l == 31) out[b] = result * LN2F;
}

/* ------------------------------------------------------------------ */
extern "C" void kernel_launch(void* const* d_in, const int* in_sizes, int n_in,
                              void* d_out, int out_size) {
    (void)in_sizes; (void)n_in; (void)out_size;
    const float* x = (const float*)d_in[0];
    const float* y = (const float*)d_in[1];
    float* out = (float*)d_out;

    dim3 gridA(256, NBATCH);
    compute_D_kernel<<<gridA, 256>>>(x, y);
    sdtw_pipeline_kernel<<<NBATCH, 1024>>>(out);
}